// round 1
// baseline (speedup 1.0000x reference)
#include <cuda_runtime.h>
#include <cuda_bf16.h>

// SplitContextCenterConv2D: masked 3x3 conv.
//   out[b,h,w,co] = sum_{(ky,kx)!=(1,1)} sum_ci ctx[b,h+ky-1,w+kx-1,ci] * K[ky,kx,0,ci,co]
//                 + sum_ci cen[b,h,w,ci] * K[1,1,1,ci,co] + bias[co]
// ctx = x[...,0:128], cen = x[...,128:256].
// x: (8,256,256,256) f32, kernel: (3,3,2,128,256) f32, bias: (256,) f32.
// out: (8,256,256,256) f32.

#define TH 8
#define TW 8
#define CIN 128
#define COUT 256
#define HH 256
#define WW 256

// Shared layout (floats):
//   sctx: 10*10*128 = 12800
//   scen:  8* 8*128 =  8192
//   swt : 16*256    =  4096
#define SCTX_F 12800
#define SCEN_F 8192
#define SWT_F 4096
#define SMEM_BYTES ((SCTX_F + SCEN_F + SWT_F) * 4)

__global__ __launch_bounds__(256, 2)
void split_conv_kernel(const float* __restrict__ x,
                       const float* __restrict__ kern,
                       const float* __restrict__ bias,
                       float* __restrict__ out) {
    extern __shared__ float smem[];
    float* sctx = smem;
    float* scen = smem + SCTX_F;
    float* swt  = smem + SCTX_F + SCEN_F;

    const int tid = threadIdx.x;
    const int tc  = tid & 15;   // channel group: owns pairs co = 32*p + 2*tc
    const int ts  = tid >> 4;   // spatial group: owns positions ts*4 .. ts*4+3

    const int b  = blockIdx.z;
    const int h0 = blockIdx.y * TH;
    const int w0 = blockIdx.x * TW;

    const long long img_base = (long long)b * HH * WW * COUT;

    // ---- Load context tile with halo (zero-padded at borders) ----
    for (int lin = tid; lin < 10 * 10 * (CIN / 4); lin += 256) {
        int ly = lin / 320;
        int r  = lin - ly * 320;
        int lx = r >> 5;
        int c4 = r & 31;
        int gh = h0 - 1 + ly;
        int gw = w0 - 1 + lx;
        float4 v = make_float4(0.f, 0.f, 0.f, 0.f);
        if ((unsigned)gh < (unsigned)HH && (unsigned)gw < (unsigned)WW) {
            v = *(const float4*)(x + img_base + ((long long)gh * WW + gw) * COUT + c4 * 4);
        }
        *(float4*)(sctx + (ly * 10 + lx) * CIN + c4 * 4) = v;
    }
    // ---- Load center tile (no halo; channels 128..255) ----
    for (int lin = tid; lin < TH * TW * (CIN / 4); lin += 256) {
        int ly = lin >> 8;
        int r  = lin & 255;
        int lx = r >> 5;
        int c4 = r & 31;
        float4 v = *(const float4*)(x + img_base +
                                    ((long long)(h0 + ly) * WW + (w0 + lx)) * COUT +
                                    CIN + c4 * 4);
        *(float4*)(scen + (ly * TW + lx) * CIN + c4 * 4) = v;
    }

    // ---- Accumulators: 4 spatial x 8 f32x2 pairs, init with bias ----
    unsigned long long acc[4][8];
#pragma unroll
    for (int p = 0; p < 8; p++) {
        unsigned long long bp = *(const unsigned long long*)(bias + p * 32 + tc * 2);
#pragma unroll
        for (int s = 0; s < 4; s++) acc[s][p] = bp;
    }

    int ly_[4], lx_[4];
#pragma unroll
    for (int s = 0; s < 4; s++) {
        int pos = ts * 4 + s;
        ly_[s] = pos >> 3;
        lx_[s] = pos & 7;
    }

    __syncthreads();

    // ---- Main loop: 9 taps x 8 cin-chunks of 16 ----
    for (int t = 0; t < 9; t++) {
        const int ky = t / 3, kx = t % 3;
        const bool center_tap = (t == 4);
        // kernel[ky][kx][io] base; io=0 for ctx taps, io=1 for the center tap.
        const float* wsrc = kern + (size_t)(t * 2 + (center_tap ? 1 : 0)) * CIN * COUT;
        const float* xsrc = center_tap ? scen : sctx;
        int base[4];
#pragma unroll
        for (int s = 0; s < 4; s++) {
            base[s] = center_tap ? (ly_[s] * TW + lx_[s]) * CIN
                                 : ((ly_[s] + ky) * 10 + (lx_[s] + kx)) * CIN;
        }

        for (int cin0 = 0; cin0 < CIN; cin0 += 16) {
            __syncthreads();  // previous chunk's readers done before overwrite
#pragma unroll
            for (int i = 0; i < 4; i++) {
                int lin = tid + i * 256;       // 0..1023 float4s
                int ci  = lin >> 6;            // 0..15
                int co4 = lin & 63;            // 0..63
                float4 wv4 = *(const float4*)(wsrc + (size_t)(cin0 + ci) * COUT + co4 * 4);
                *(float4*)(swt + ci * COUT + co4 * 4) = wv4;
            }
            __syncthreads();

#pragma unroll
            for (int ci = 0; ci < 16; ci++) {
                unsigned long long wv[8];
                const float* wrow = swt + ci * COUT + tc * 2;
#pragma unroll
                for (int p = 0; p < 8; p++)
                    wv[p] = *(const unsigned long long*)(wrow + p * 32);
#pragma unroll
                for (int s = 0; s < 4; s++) {
                    float xv = xsrc[base[s] + cin0 + ci];
                    unsigned long long xx;
                    asm("mov.b64 %0, {%1, %1};" : "=l"(xx) : "f"(xv));
#pragma unroll
                    for (int p = 0; p < 8; p++)
                        asm("fma.rn.f32x2 %0, %1, %2, %0;"
                            : "+l"(acc[s][p]) : "l"(xx), "l"(wv[p]));
                }
            }
        }
    }

    // ---- Store ----
#pragma unroll
    for (int s = 0; s < 4; s++) {
        float* optr = out + img_base +
                      ((long long)(h0 + ly_[s]) * WW + (w0 + lx_[s])) * COUT + tc * 2;
#pragma unroll
        for (int p = 0; p < 8; p++)
            *(unsigned long long*)(optr + p * 32) = acc[s][p];
    }
}

extern "C" void kernel_launch(void* const* d_in, const int* in_sizes, int n_in,
                              void* d_out, int out_size) {
    (void)in_sizes; (void)n_in; (void)out_size;
    const float* x    = (const float*)d_in[0];
    const float* kern = (const float*)d_in[1];
    const float* bias = (const float*)d_in[2];
    float* out = (float*)d_out;

    cudaFuncSetAttribute(split_conv_kernel,
                         cudaFuncAttributeMaxDynamicSharedMemorySize, SMEM_BYTES);

    dim3 grid(WW / TW, HH / TH, 8);
    dim3 block(256);
    split_conv_kernel<<<grid, block, SMEM_BYTES>>>(x, kern, bias, out);
}

// round 3
// speedup vs baseline: 3.1697x; 3.1697x over previous
#include <cuda_runtime.h>
#include <cstdint>

// SplitContextCenterConv2D as implicit GEMM on warp-level tf32 mma.sync
// (tcgen05 unavailable: harness PTX targets compute_103, not 103a).
// out[b,h,w,n] = sum_{t=0..8} sum_ci A_t(pix,ci) * W_t(ci,n) + bias[n]
//   t!=4: A = x[b, h+ky-1, w+kx-1, ci]   (ctx channels 0..127), W = kernel[ky,kx,0,ci,n]
//   t==4: A = x[b, h, w, 128+ci]         (center channels),     W = kernel[1,1,1,ci,n]
// GEMM: M = 8*256*256, N = 256, K = 1152 in 36 chunks of 32.

#define HH 256
#define WW 256
#define CIN 128
#define COUT 256
#define KTOT 1152
#define NCHUNK 36

#define STRIDE 36                    // floats per smem row (128B data + 16B pad)
#define A_FLOATS (128 * STRIDE)      // 4608
#define B_FLOATS (256 * STRIDE)      // 9216
#define STAGE_FLOATS (A_FLOATS + B_FLOATS)
#define SMEM_BYTES (2 * STAGE_FLOATS * 4)   // 110592

__device__ float g_wt[COUT * KTOT];  // tf32(rna) bit patterns, layout [n][k]

static __device__ __forceinline__ uint32_t f2tf32(float f) {
    uint32_t r;
    asm("cvt.rna.tf32.f32 %0, %1;" : "=r"(r) : "f"(f));
    return r;
}

__global__ void wt_transform(const float* __restrict__ kern) {
    int o = blockIdx.x * 256 + threadIdx.x;
    if (o >= COUT * KTOT) return;
    int n = o / KTOT;
    int k = o - n * KTOT;
    int t = k >> 7;
    int ci = k & 127;
    int io = (t == 4) ? 1 : 0;
    float v = kern[(size_t)((t * 2 + io) * CIN + ci) * COUT + n];
    g_wt[o] = __uint_as_float(f2tf32(v));
}

static __device__ __forceinline__ void cp16(uint32_t dst, const void* src, uint32_t sz) {
    asm volatile("cp.async.cg.shared.global [%0], [%1], 16, %2;"
                 :: "r"(dst), "l"(src), "r"(sz) : "memory");
}

__global__ __launch_bounds__(256, 1)
void conv_mma(const float* __restrict__ x, const float* __restrict__ bias,
              float* __restrict__ out) {
    extern __shared__ float smem[];
    const uint32_t smem_b = (uint32_t)__cvta_generic_to_shared(smem);

    const int tid = threadIdx.x;
    const int wid = tid >> 5;
    const int lane = tid & 31;
    const int g   = lane >> 2;   // group id (0..7)
    const int tig = lane & 3;    // thread in group

    const int warp_m = wid & 1;        // 2 warps over M
    const int warp_n = wid >> 1;       // 4 warps over N
    const int m0 = warp_m * 64;
    const int n0 = warp_n * 64;

    const int b  = blockIdx.z;
    const int h  = blockIdx.y;
    const int w0 = blockIdx.x * 128;
    const size_t img = (size_t)b * HH * WW * COUT;

    // per-thread prefetch coords: A -> 4 x 16B, B -> 8 x 16B
    const int am = tid >> 1;                 // 0..127 (row), two threads per row
    const int aj0 = (tid & 1) * 4;           // j in {0..3} or {4..7}

    float acc[4][8][4];
#pragma unroll
    for (int mi = 0; mi < 4; mi++)
#pragma unroll
        for (int ni = 0; ni < 8; ni++)
#pragma unroll
            for (int r = 0; r < 4; r++) acc[mi][ni][r] = 0.f;

    // ---------------- prefetch helper (macro-ish lambda) ----------------
    auto prefetch = [&](int c) {
        const int stage = c & 1;
        const uint32_t aS = smem_b + stage * (STAGE_FLOATS * 4);
        const uint32_t bS = aS + A_FLOATS * 4;
        const int t   = c >> 2;
        const int ci0 = (c & 3) << 5;
        const bool cen = (t == 4);
        const int ky = t / 3, kx = t % 3;
        const int gh = cen ? h : (h + ky - 1);
        const bool rowok = cen || ((unsigned)gh < HH);
        const int ghc = rowok ? gh : 0;
        const int chOff = cen ? (CIN + ci0) : ci0;
        const float* srow = x + img + (size_t)ghc * WW * COUT + chOff;

        // A tile: rows m = 0..127, each row 8 x 16B of k
#pragma unroll
        for (int i = 0; i < 2; i++) {
            int m = am;
            int j = aj0 + i * (aj0 ? -4 : 4);  // not used; simpler below
        }
        // two 16B segs per thread covering j = aj0..aj0+3 ... use explicit loop:
#pragma unroll
        for (int jj = 0; jj < 4; jj += 2) {
            // each thread does 2 of its 4 j-slots per iteration? -> total 4 segs:
        }
        // (explicit, simple version: 4 segments per thread)
#pragma unroll
        for (int i = 0; i < 4; i++) {
            int e = tid + i * 256;             // 0..1023
            int m = e >> 3, j = e & 7;
            int gw = cen ? (w0 + m) : (w0 + m + kx - 1);
            bool ok = rowok && ((unsigned)gw < (unsigned)WW);
            int gwc = ok ? gw : 0;
            uint32_t dst = aS + (uint32_t)(m * STRIDE + j * 4) * 4;
            cp16(dst, srow + (size_t)gwc * COUT + j * 4, ok ? 16 : 0);
        }
        // B tile: n = 0..255, 8 x 16B of k each
        const float* wsrc = g_wt + (size_t)c * 32;
#pragma unroll
        for (int i = 0; i < 8; i++) {
            int e = tid + i * 256;             // 0..2047
            int n = e >> 3, j = e & 7;
            uint32_t dst = bS + (uint32_t)(n * STRIDE + j * 4) * 4;
            cp16(dst, wsrc + (size_t)n * KTOT + j * 4, 16);
        }
        asm volatile("cp.async.commit_group;" ::: "memory");
    };

    prefetch(0);

    for (int c = 0; c < NCHUNK; c++) {
        if (c + 1 < NCHUNK) prefetch(c + 1);
        if (c + 1 < NCHUNK)
            asm volatile("cp.async.wait_group 1;" ::: "memory");
        else
            asm volatile("cp.async.wait_group 0;" ::: "memory");
        __syncthreads();

        const int stage = c & 1;
        const float* sA = smem + stage * STAGE_FLOATS;
        const float* sB = sA + A_FLOATS;

#pragma unroll
        for (int kk = 0; kk < 4; kk++) {
            const int k0 = kk * 8;
            float a[4][4];
#pragma unroll
            for (int mi = 0; mi < 4; mi++) {
                const float* ap = sA + (m0 + mi * 16 + g) * STRIDE + k0 + tig;
                a[mi][0] = ap[0];
                a[mi][1] = ap[8 * STRIDE];
                a[mi][2] = ap[4];
                a[mi][3] = ap[8 * STRIDE + 4];
            }
            float bb[8][2];
#pragma unroll
            for (int ni = 0; ni < 8; ni++) {
                const float* bp = sB + (n0 + ni * 8 + g) * STRIDE + k0 + tig;
                bb[ni][0] = bp[0];
                bb[ni][1] = bp[4];
            }
#pragma unroll
            for (int mi = 0; mi < 4; mi++)
#pragma unroll
                for (int ni = 0; ni < 8; ni++)
                    asm volatile(
                        "mma.sync.aligned.m16n8k8.row.col.f32.tf32.tf32.f32 "
                        "{%0,%1,%2,%3}, {%4,%5,%6,%7}, {%8,%9}, {%0,%1,%2,%3};"
                        : "+f"(acc[mi][ni][0]), "+f"(acc[mi][ni][1]),
                          "+f"(acc[mi][ni][2]), "+f"(acc[mi][ni][3])
                        : "f"(a[mi][0]), "f"(a[mi][1]), "f"(a[mi][2]), "f"(a[mi][3]),
                          "f"(bb[ni][0]), "f"(bb[ni][1]));
        }
        __syncthreads();
    }

    // ---------------- epilogue ----------------
    // c-frag: c0 at (row=g, col=2*tig), c1 col+1, c2 row+8, c3 row+8 col+1
    float bv[8][2];
#pragma unroll
    for (int ni = 0; ni < 8; ni++) {
        int n = n0 + ni * 8 + tig * 2;
        bv[ni][0] = bias[n];
        bv[ni][1] = bias[n + 1];
    }
#pragma unroll
    for (int mi = 0; mi < 4; mi++) {
        int r0 = m0 + mi * 16 + g;
        float* p0 = out + img + ((size_t)h * WW + (w0 + r0)) * COUT;
        float* p1 = out + img + ((size_t)h * WW + (w0 + r0 + 8)) * COUT;
#pragma unroll
        for (int ni = 0; ni < 8; ni++) {
            int n = n0 + ni * 8 + tig * 2;
            float2 v0 = make_float2(acc[mi][ni][0] + bv[ni][0],
                                    acc[mi][ni][1] + bv[ni][1]);
            float2 v1 = make_float2(acc[mi][ni][2] + bv[ni][0],
                                    acc[mi][ni][3] + bv[ni][1]);
            *(float2*)(p0 + n) = v0;
            *(float2*)(p1 + n) = v1;
        }
    }
}

extern "C" void kernel_launch(void* const* d_in, const int* in_sizes, int n_in,
                              void* d_out, int out_size) {
    (void)in_sizes; (void)n_in; (void)out_size;
    const float* x    = (const float*)d_in[0];
    const float* kern = (const float*)d_in[1];
    const float* bias = (const float*)d_in[2];
    float* out = (float*)d_out;

    wt_transform<<<(COUT * KTOT + 255) / 256, 256>>>(kern);

    cudaFuncSetAttribute(conv_mma, cudaFuncAttributeMaxDynamicSharedMemorySize, SMEM_BYTES);
    dim3 grid(WW / 128, HH, 8);
    conv_mma<<<grid, 256, SMEM_BYTES>>>(x, bias, out);
}

// round 5
// speedup vs baseline: 3.2115x; 1.0132x over previous
#include <cuda_runtime.h>
#include <cstdint>

// SplitContextCenterConv2D as implicit GEMM on warp-level tf32 mma.sync.
// GEMM: M = 8*256*256 pixels, N = 256, K = 9*128 = 1152 (36 chunks of 32).
// This round: CTA tile 128x128 (M x N), 2 CTAs/SM (<=128 regs, 72KB smem).

#define HH 256
#define WW 256
#define CIN 128
#define COUT 256
#define KTOT 1152
#define NCHUNK 36

#define STRIDE 36                    // floats per smem row (128B data + 16B pad)
#define A_FLOATS (128 * STRIDE)      // 4608
#define B_FLOATS (128 * STRIDE)      // 4608
#define STAGE_FLOATS (A_FLOATS + B_FLOATS)
#define SMEM_BYTES (2 * STAGE_FLOATS * 4)   // 73728

__device__ float g_wt[COUT * KTOT];  // tf32(rna) bit patterns, layout [n][k]

static __device__ __forceinline__ uint32_t f2tf32(float f) {
    uint32_t r;
    asm("cvt.rna.tf32.f32 %0, %1;" : "=r"(r) : "f"(f));
    return r;
}

__global__ void wt_transform(const float* __restrict__ kern) {
    int o = blockIdx.x * 256 + threadIdx.x;
    if (o >= COUT * KTOT) return;
    int n = o / KTOT;
    int k = o - n * KTOT;
    int t = k >> 7;
    int ci = k & 127;
    int io = (t == 4) ? 1 : 0;
    float v = kern[(size_t)((t * 2 + io) * CIN + ci) * COUT + n];
    g_wt[o] = __uint_as_float(f2tf32(v));
}

static __device__ __forceinline__ void cp16(uint32_t dst, const void* src, uint32_t sz) {
    asm volatile("cp.async.cg.shared.global [%0], [%1], 16, %2;"
                 :: "r"(dst), "l"(src), "r"(sz) : "memory");
}

__global__ __launch_bounds__(256, 2)
void conv_mma(const float* __restrict__ x, const float* __restrict__ bias,
              float* __restrict__ out) {
    extern __shared__ float smem[];
    const uint32_t smem_b = (uint32_t)__cvta_generic_to_shared(smem);

    const int tid  = threadIdx.x;
    const int wid  = tid >> 5;
    const int lane = tid & 31;
    const int g    = lane >> 2;   // 0..7
    const int tig  = lane & 3;    // 0..3

    const int m0 = (wid & 1) * 64;   // warp M offset (2 warps over M=128)
    const int n0 = (wid >> 1) * 32;  // warp N offset (4 warps over N=128)

    const int b  = blockIdx.z;
    const int h  = blockIdx.y;
    const int w0 = (blockIdx.x >> 1) * 128;
    const int nb = (blockIdx.x & 1) * 128;      // N half
    const size_t img = (size_t)b * HH * WW * COUT;

    float acc[4][4][4];
#pragma unroll
    for (int mi = 0; mi < 4; mi++)
#pragma unroll
        for (int ni = 0; ni < 4; ni++)
#pragma unroll
            for (int r = 0; r < 4; r++) acc[mi][ni][r] = 0.f;

    auto prefetch = [&](int c) {
        const int stage = c & 1;
        const uint32_t aS = smem_b + stage * (STAGE_FLOATS * 4);
        const uint32_t bS = aS + A_FLOATS * 4;
        const int t   = c >> 2;
        const int ci0 = (c & 3) << 5;
        const bool cen = (t == 4);
        const int ky = t / 3, kx = t % 3;
        const int gh = cen ? h : (h + ky - 1);
        const bool rowok = cen || ((unsigned)gh < HH);
        const int ghc = rowok ? gh : 0;
        const int chOff = cen ? (CIN + ci0) : ci0;
        const float* srow = x + img + (size_t)ghc * WW * COUT + chOff;

        // A tile: 128 rows x 8 x 16B
#pragma unroll
        for (int i = 0; i < 4; i++) {
            int e = tid + i * 256;             // 0..1023
            int m = e >> 3, j = e & 7;
            int gw = cen ? (w0 + m) : (w0 + m + kx - 1);
            bool ok = rowok && ((unsigned)gw < (unsigned)WW);
            int gwc = ok ? gw : 0;
            uint32_t dst = aS + (uint32_t)(m * STRIDE + j * 4) * 4;
            cp16(dst, srow + (size_t)gwc * COUT + j * 4, ok ? 16 : 0);
        }
        // B tile: 128 rows (n = nb..nb+127) x 8 x 16B
        const float* wsrc = g_wt + (size_t)(nb) * KTOT + (size_t)c * 32;
#pragma unroll
        for (int i = 0; i < 4; i++) {
            int e = tid + i * 256;             // 0..1023
            int n = e >> 3, j = e & 7;
            uint32_t dst = bS + (uint32_t)(n * STRIDE + j * 4) * 4;
            cp16(dst, wsrc + (size_t)n * KTOT + j * 4, 16);
        }
        asm volatile("cp.async.commit_group;" ::: "memory");
    };

    prefetch(0);

    for (int c = 0; c < NCHUNK; c++) {
        if (c + 1 < NCHUNK) {
            prefetch(c + 1);
            asm volatile("cp.async.wait_group 1;" ::: "memory");
        } else {
            asm volatile("cp.async.wait_group 0;" ::: "memory");
        }
        __syncthreads();

        const int stage = c & 1;
        const float* sA = smem + stage * STAGE_FLOATS;
        const float* sB = sA + A_FLOATS;

#pragma unroll
        for (int kk = 0; kk < 4; kk++) {
            const int k0 = kk * 8;
            float a[4][4];
#pragma unroll
            for (int mi = 0; mi < 4; mi++) {
                const float* ap = sA + (m0 + mi * 16 + g) * STRIDE + k0 + tig;
                a[mi][0] = ap[0];
                a[mi][1] = ap[8 * STRIDE];
                a[mi][2] = ap[4];
                a[mi][3] = ap[8 * STRIDE + 4];
            }
            float bb[4][2];
#pragma unroll
            for (int ni = 0; ni < 4; ni++) {
                const float* bp = sB + (n0 + ni * 8 + g) * STRIDE + k0 + tig;
                bb[ni][0] = bp[0];
                bb[ni][1] = bp[4];
            }
#pragma unroll
            for (int mi = 0; mi < 4; mi++)
#pragma unroll
                for (int ni = 0; ni < 4; ni++)
                    asm volatile(
                        "mma.sync.aligned.m16n8k8.row.col.f32.tf32.tf32.f32 "
                        "{%0,%1,%2,%3}, {%4,%5,%6,%7}, {%8,%9}, {%0,%1,%2,%3};"
                        : "+f"(acc[mi][ni][0]), "+f"(acc[mi][ni][1]),
                          "+f"(acc[mi][ni][2]), "+f"(acc[mi][ni][3])
                        : "f"(a[mi][0]), "f"(a[mi][1]), "f"(a[mi][2]), "f"(a[mi][3]),
                          "f"(bb[ni][0]), "f"(bb[ni][1]));
        }
        __syncthreads();
    }

    // ---------------- epilogue ----------------
    float bv[4][2];
#pragma unroll
    for (int ni = 0; ni < 4; ni++) {
        int n = nb + n0 + ni * 8 + tig * 2;
        bv[ni][0] = bias[n];
        bv[ni][1] = bias[n + 1];
    }
#pragma unroll
    for (int mi = 0; mi < 4; mi++) {
        int r0 = m0 + mi * 16 + g;
        float* p0 = out + img + ((size_t)h * WW + (w0 + r0)) * COUT;
        float* p1 = out + img + ((size_t)h * WW + (w0 + r0 + 8)) * COUT;
#pragma unroll
        for (int ni = 0; ni < 4; ni++) {
            int n = nb + n0 + ni * 8 + tig * 2;
            float2 v0 = make_float2(acc[mi][ni][0] + bv[ni][0],
                                    acc[mi][ni][1] + bv[ni][1]);
            float2 v1 = make_float2(acc[mi][ni][2] + bv[ni][0],
                                    acc[mi][ni][3] + bv[ni][1]);
            *(float2*)(p0 + n) = v0;
            *(float2*)(p1 + n) = v1;
        }
    }
}

extern "C" void kernel_launch(void* const* d_in, const int* in_sizes, int n_in,
                              void* d_out, int out_size) {
    (void)in_sizes; (void)n_in; (void)out_size;
    const float* x    = (const float*)d_in[0];
    const float* kern = (const float*)d_in[1];
    const float* bias = (const float*)d_in[2];
    float* out = (float*)d_out;

    wt_transform<<<(COUT * KTOT + 255) / 256, 256>>>(kern);

    cudaFuncSetAttribute(conv_mma, cudaFuncAttributeMaxDynamicSharedMemorySize, SMEM_BYTES);
    dim3 grid((WW / 128) * (COUT / 128), HH, 8);   // (4, 256, 8) = 8192 CTAs
    conv_mma<<<grid, 256, SMEM_BYTES>>>(x, bias, out);
}

// round 7
// speedup vs baseline: 3.6153x; 1.1257x over previous
#include <cuda_runtime.h>
#include <cstdint>

// SplitContextCenterConv2D as implicit GEMM on warp-level tf32 mma.sync.
// GEMM: M = 8*256*256 pixels, N = 256, K = 9*128 = 1152 (36 chunks of 32).
// CTA tile 128x128, 2 CTAs/SM. This round: float2 fragment loads via
// consistent k-slot pairing, conflict-free STRIDE=40, 1 barrier per chunk.

#define HH 256
#define WW 256
#define CIN 128
#define COUT 256
#define KTOT 1152
#define NCHUNK 36

#define STRIDE 40                    // floats per smem row (128B data + 32B pad)
#define A_FLOATS (128 * STRIDE)      // 5120
#define B_FLOATS (128 * STRIDE)      // 5120
#define STAGE_FLOATS (A_FLOATS + B_FLOATS)
#define SMEM_BYTES (2 * STAGE_FLOATS * 4)   // 81920

__device__ float g_wt[COUT * KTOT];  // tf32(rna) bit patterns, layout [n][k]

static __device__ __forceinline__ uint32_t f2tf32(float f) {
    uint32_t r;
    asm("cvt.rna.tf32.f32 %0, %1;" : "=r"(r) : "f"(f));
    return r;
}

__global__ void wt_transform(const float* __restrict__ kern) {
    int o = blockIdx.x * 256 + threadIdx.x;
    if (o >= COUT * KTOT) return;
    int n = o / KTOT;
    int k = o - n * KTOT;
    int t = k >> 7;
    int ci = k & 127;
    int io = (t == 4) ? 1 : 0;
    float v = kern[(size_t)((t * 2 + io) * CIN + ci) * COUT + n];
    g_wt[o] = __uint_as_float(f2tf32(v));
}

static __device__ __forceinline__ void cp16(uint32_t dst, const void* src, uint32_t sz) {
    asm volatile("cp.async.cg.shared.global [%0], [%1], 16, %2;"
                 :: "r"(dst), "l"(src), "r"(sz) : "memory");
}

__global__ __launch_bounds__(256, 2)
void conv_mma(const float* __restrict__ x, const float* __restrict__ bias,
              float* __restrict__ out) {
    extern __shared__ float smem[];
    const uint32_t smem_b = (uint32_t)__cvta_generic_to_shared(smem);

    const int tid  = threadIdx.x;
    const int wid  = tid >> 5;
    const int lane = tid & 31;
    const int g    = lane >> 2;   // 0..7
    const int tig  = lane & 3;    // 0..3

    const int m0 = (wid & 1) * 64;   // warp M offset (2 warps over M=128)
    const int n0 = (wid >> 1) * 32;  // warp N offset (4 warps over N=128)

    const int b  = blockIdx.z;
    const int h  = blockIdx.y;
    const int w0 = (blockIdx.x >> 1) * 128;
    const int nb = (blockIdx.x & 1) * 128;      // N half
    const size_t img = (size_t)b * HH * WW * COUT;

    float acc[4][4][4];
#pragma unroll
    for (int mi = 0; mi < 4; mi++)
#pragma unroll
        for (int ni = 0; ni < 4; ni++)
#pragma unroll
            for (int r = 0; r < 4; r++) acc[mi][ni][r] = 0.f;

    auto prefetch = [&](int c) {
        const int stage = c & 1;
        const uint32_t aS = smem_b + stage * (STAGE_FLOATS * 4);
        const uint32_t bS = aS + A_FLOATS * 4;
        const int t   = c >> 2;
        const int ci0 = (c & 3) << 5;
        const bool cen = (t == 4);
        const int ky = t / 3, kx = t % 3;
        const int gh = cen ? h : (h + ky - 1);
        const bool rowok = cen || ((unsigned)gh < HH);
        const int ghc = rowok ? gh : 0;
        const int chOff = cen ? (CIN + ci0) : ci0;
        const float* srow = x + img + (size_t)ghc * WW * COUT + chOff;

        // A tile: 128 rows x 8 x 16B of k
#pragma unroll
        for (int i = 0; i < 4; i++) {
            int e = tid + i * 256;             // 0..1023
            int m = e >> 3, j = e & 7;
            int gw = cen ? (w0 + m) : (w0 + m + kx - 1);
            bool ok = rowok && ((unsigned)gw < (unsigned)WW);
            int gwc = ok ? gw : 0;
            uint32_t dst = aS + (uint32_t)(m * STRIDE + j * 4) * 4;
            cp16(dst, srow + (size_t)gwc * COUT + j * 4, ok ? 16 : 0);
        }
        // B tile: 128 rows (n = nb..nb+127) x 8 x 16B of k
        const float* wsrc = g_wt + (size_t)nb * KTOT + (size_t)c * 32;
#pragma unroll
        for (int i = 0; i < 4; i++) {
            int e = tid + i * 256;             // 0..1023
            int n = e >> 3, j = e & 7;
            uint32_t dst = bS + (uint32_t)(n * STRIDE + j * 4) * 4;
            cp16(dst, wsrc + (size_t)n * KTOT + j * 4, 16);
        }
        asm volatile("cp.async.commit_group;" ::: "memory");
    };

    prefetch(0);

    for (int c = 0; c < NCHUNK; c++) {
        asm volatile("cp.async.wait_group 0;" ::: "memory");
        __syncthreads();
        // Safe to issue next prefetch now: the barrier guarantees every warp
        // finished reading the opposite stage (iteration c-1).
        if (c + 1 < NCHUNK) prefetch(c + 1);

        const int stage = c & 1;
        const float* sA = smem + stage * STAGE_FLOATS;
        const float* sB = sA + A_FLOATS;

        // k-slot pairing: smem position 2t feeds MMA slot t, position 2t+1
        // feeds slot t+4 — applied identically to A and B, so the contraction
        // pairs the same ci on both operands (order within k is free).
#pragma unroll
        for (int kk = 0; kk < 4; kk++) {
            const int k0 = kk * 8;
            float2 aF[4][2];
#pragma unroll
            for (int mi = 0; mi < 4; mi++) {
                const float* ap = sA + (m0 + mi * 16 + g) * STRIDE + k0 + 2 * tig;
                aF[mi][0] = *(const float2*)ap;                 // row g   : slots (tig, tig+4)
                aF[mi][1] = *(const float2*)(ap + 8 * STRIDE);  // row g+8 : slots (tig, tig+4)
            }
            float2 bF[4];
#pragma unroll
            for (int ni = 0; ni < 4; ni++) {
                const float* bp = sB + (n0 + ni * 8 + g) * STRIDE + k0 + 2 * tig;
                bF[ni] = *(const float2*)bp;
            }
#pragma unroll
            for (int mi = 0; mi < 4; mi++)
#pragma unroll
                for (int ni = 0; ni < 4; ni++)
                    asm volatile(
                        "mma.sync.aligned.m16n8k8.row.col.f32.tf32.tf32.f32 "
                        "{%0,%1,%2,%3}, {%4,%5,%6,%7}, {%8,%9}, {%0,%1,%2,%3};"
                        : "+f"(acc[mi][ni][0]), "+f"(acc[mi][ni][1]),
                          "+f"(acc[mi][ni][2]), "+f"(acc[mi][ni][3])
                        : "f"(aF[mi][0].x), "f"(aF[mi][1].x),
                          "f"(aF[mi][0].y), "f"(aF[mi][1].y),
                          "f"(bF[ni].x), "f"(bF[ni].y));
        }
    }

    // ---------------- epilogue ----------------
    float bv[4][2];
#pragma unroll
    for (int ni = 0; ni < 4; ni++) {
        int n = nb + n0 + ni * 8 + tig * 2;
        bv[ni][0] = bias[n];
        bv[ni][1] = bias[n + 1];
    }
#pragma unroll
    for (int mi = 0; mi < 4; mi++) {
        int r0 = m0 + mi * 16 + g;
        float* p0 = out + img + ((size_t)h * WW + (w0 + r0)) * COUT;
        float* p1 = out + img + ((size_t)h * WW + (w0 + r0 + 8)) * COUT;
#pragma unroll
        for (int ni = 0; ni < 4; ni++) {
            int n = nb + n0 + ni * 8 + tig * 2;
            float2 v0 = make_float2(acc[mi][ni][0] + bv[ni][0],
                                    acc[mi][ni][1] + bv[ni][1]);
            float2 v1 = make_float2(acc[mi][ni][2] + bv[ni][0],
                                    acc[mi][ni][3] + bv[ni][1]);
            *(float2*)(p0 + n) = v0;
            *(float2*)(p1 + n) = v1;
        }
    }
}

extern "C" void kernel_launch(void* const* d_in, const int* in_sizes, int n_in,
                              void* d_out, int out_size) {
    (void)in_sizes; (void)n_in; (void)out_size;
    const float* x    = (const float*)d_in[0];
    const float* kern = (const float*)d_in[1];
    const float* bias = (const float*)d_in[2];
    float* out = (float*)d_out;

    wt_transform<<<(COUT * KTOT + 255) / 256, 256>>>(kern);

    cudaFuncSetAttribute(conv_mma, cudaFuncAttributeMaxDynamicSharedMemorySize, SMEM_BYTES);
    dim3 grid((WW / 128) * (COUT / 128), HH, 8);   // (4, 256, 8) = 8192 CTAs
    conv_mma<<<grid, 256, SMEM_BYTES>>>(x, bias, out);
}

// round 8
// speedup vs baseline: 3.7694x; 1.0426x over previous
#include <cuda_runtime.h>
#include <cstdint>

// SplitContextCenterConv2D as implicit GEMM on warp-level tf32 mma.sync.
// GEMM: M = 8*256*256 pixels, N = 256, K = 9*128 = 1152 (36 chunks of 32).
// CTA tile 128x128, 2 CTAs/SM, 1 barrier/chunk, float2 fragment loads.
// This round: FULL UNROLL of the chunk loop -> all tap/offset math folds to
// compile-time constants, removing the ALU/IMAD co-bottleneck.

#define HH 256
#define WW 256
#define CIN 128
#define COUT 256
#define KTOT 1152
#define NCHUNK 36

#define STRIDE 40                    // floats per smem row (128B data + 32B pad)
#define A_FLOATS (128 * STRIDE)      // 5120
#define B_FLOATS (128 * STRIDE)      // 5120
#define STAGE_FLOATS (A_FLOATS + B_FLOATS)
#define SMEM_BYTES (2 * STAGE_FLOATS * 4)   // 81920

__device__ float g_wt[COUT * KTOT];  // tf32(rna) bit patterns, layout [n][k]

static __device__ __forceinline__ uint32_t f2tf32(float f) {
    uint32_t r;
    asm("cvt.rna.tf32.f32 %0, %1;" : "=r"(r) : "f"(f));
    return r;
}

__global__ void wt_transform(const float* __restrict__ kern) {
    int o = blockIdx.x * 256 + threadIdx.x;
    if (o >= COUT * KTOT) return;
    int n = o / KTOT;
    int k = o - n * KTOT;
    int t = k >> 7;
    int ci = k & 127;
    int io = (t == 4) ? 1 : 0;
    float v = kern[(size_t)((t * 2 + io) * CIN + ci) * COUT + n];
    g_wt[o] = __uint_as_float(f2tf32(v));
}

static __device__ __forceinline__ void cp16(uint32_t dst, const void* src, uint32_t sz) {
    asm volatile("cp.async.cg.shared.global [%0], [%1], 16, %2;"
                 :: "r"(dst), "l"(src), "r"(sz) : "memory");
}

__global__ __launch_bounds__(256, 2)
void conv_mma(const float* __restrict__ x, const float* __restrict__ bias,
              float* __restrict__ out) {
    extern __shared__ float smem[];
    const uint32_t smem_b = (uint32_t)__cvta_generic_to_shared(smem);

    const int tid  = threadIdx.x;
    const int wid  = tid >> 5;
    const int lane = tid & 31;
    const int g    = lane >> 2;   // 0..7
    const int tig  = lane & 3;    // 0..3

    const int m0 = (wid & 1) * 64;   // warp M offset (2 warps over M=128)
    const int n0 = (wid >> 1) * 32;  // warp N offset (4 warps over N=128)

    const int b  = blockIdx.z;
    const int h  = blockIdx.y;
    const int w0 = (blockIdx.x >> 1) * 128;
    const int nb = (blockIdx.x & 1) * 128;      // N half
    const size_t img = (size_t)b * HH * WW * COUT;

    // hoisted per-thread prefetch coords (compile-time folded after unroll)
    const int pm = tid >> 1;            // not used directly; kept simple below

    float acc[4][4][4];
#pragma unroll
    for (int mi = 0; mi < 4; mi++)
#pragma unroll
        for (int ni = 0; ni < 4; ni++)
#pragma unroll
            for (int r = 0; r < 4; r++) acc[mi][ni][r] = 0.f;

    auto prefetch = [&](int c) {
        const int stage = c & 1;
        const uint32_t aS = smem_b + stage * (STAGE_FLOATS * 4);
        const uint32_t bS = aS + A_FLOATS * 4;
        const int t   = c >> 2;          // compile-time after unroll
        const int ci0 = (c & 3) << 5;
        const bool cen = (t == 4);
        const int ky = t / 3, kx = t % 3;
        const int gh = cen ? h : (h + ky - 1);
        const bool rowok = cen || ((unsigned)gh < HH);
        const int ghc = rowok ? gh : 0;
        const int chOff = cen ? (CIN + ci0) : ci0;
        const float* srow = x + img + (size_t)ghc * WW * COUT + chOff;

        // A tile: 128 rows x 8 x 16B of k
#pragma unroll
        for (int i = 0; i < 4; i++) {
            int e = tid + i * 256;             // 0..1023
            int m = e >> 3, j = e & 7;
            int gw = cen ? (w0 + m) : (w0 + m + kx - 1);
            bool ok = rowok && ((unsigned)gw < (unsigned)WW);
            int gwc = ok ? gw : 0;
            uint32_t dst = aS + (uint32_t)(m * STRIDE + j * 4) * 4;
            cp16(dst, srow + (size_t)gwc * COUT + j * 4, ok ? 16 : 0);
        }
        // B tile: 128 rows (n = nb..nb+127) x 8 x 16B of k
        const float* wsrc = g_wt + (size_t)nb * KTOT + (size_t)c * 32;
#pragma unroll
        for (int i = 0; i < 4; i++) {
            int e = tid + i * 256;             // 0..1023
            int n = e >> 3, j = e & 7;
            uint32_t dst = bS + (uint32_t)(n * STRIDE + j * 4) * 4;
            cp16(dst, wsrc + (size_t)n * KTOT + j * 4, 16);
        }
        asm volatile("cp.async.commit_group;" ::: "memory");
    };

    prefetch(0);

#pragma unroll
    for (int c = 0; c < NCHUNK; c++) {
        asm volatile("cp.async.wait_group 0;" ::: "memory");
        __syncthreads();
        // Barrier guarantees all warps finished reading the opposite stage.
        if (c + 1 < NCHUNK) prefetch(c + 1);

        const int stage = c & 1;
        const float* sA = smem + stage * STAGE_FLOATS;
        const float* sB = sA + A_FLOATS;

        // k-slot pairing: smem position 2t -> MMA slot t, 2t+1 -> slot t+4,
        // applied identically to A and B (contraction order within k is free).
#pragma unroll
        for (int kk = 0; kk < 4; kk++) {
            const int k0 = kk * 8;
            float2 aF[4][2];
#pragma unroll
            for (int mi = 0; mi < 4; mi++) {
                const float* ap = sA + (m0 + mi * 16 + g) * STRIDE + k0 + 2 * tig;
                aF[mi][0] = *(const float2*)ap;                 // row g
                aF[mi][1] = *(const float2*)(ap + 8 * STRIDE);  // row g+8
            }
            float2 bF[4];
#pragma unroll
            for (int ni = 0; ni < 4; ni++) {
                const float* bp = sB + (n0 + ni * 8 + g) * STRIDE + k0 + 2 * tig;
                bF[ni] = *(const float2*)bp;
            }
#pragma unroll
            for (int mi = 0; mi < 4; mi++)
#pragma unroll
                for (int ni = 0; ni < 4; ni++)
                    asm volatile(
                        "mma.sync.aligned.m16n8k8.row.col.f32.tf32.tf32.f32 "
                        "{%0,%1,%2,%3}, {%4,%5,%6,%7}, {%8,%9}, {%0,%1,%2,%3};"
                        : "+f"(acc[mi][ni][0]), "+f"(acc[mi][ni][1]),
                          "+f"(acc[mi][ni][2]), "+f"(acc[mi][ni][3])
                        : "f"(aF[mi][0].x), "f"(aF[mi][1].x),
                          "f"(aF[mi][0].y), "f"(aF[mi][1].y),
                          "f"(bF[ni].x), "f"(bF[ni].y));
        }
    }

    // ---------------- epilogue ----------------
    float bv[4][2];
#pragma unroll
    for (int ni = 0; ni < 4; ni++) {
        int n = nb + n0 + ni * 8 + tig * 2;
        bv[ni][0] = bias[n];
        bv[ni][1] = bias[n + 1];
    }
#pragma unroll
    for (int mi = 0; mi < 4; mi++) {
        int r0 = m0 + mi * 16 + g;
        float* p0 = out + img + ((size_t)h * WW + (w0 + r0)) * COUT;
        float* p1 = out + img + ((size_t)h * WW + (w0 + r0 + 8)) * COUT;
#pragma unroll
        for (int ni = 0; ni < 4; ni++) {
            int n = nb + n0 + ni * 8 + tig * 2;
            float2 v0 = make_float2(acc[mi][ni][0] + bv[ni][0],
                                    acc[mi][ni][1] + bv[ni][1]);
            float2 v1 = make_float2(acc[mi][ni][2] + bv[ni][0],
                                    acc[mi][ni][3] + bv[ni][1]);
            *(float2*)(p0 + n) = v0;
            *(float2*)(p1 + n) = v1;
        }
    }
}

extern "C" void kernel_launch(void* const* d_in, const int* in_sizes, int n_in,
                              void* d_out, int out_size) {
    (void)in_sizes; (void)n_in; (void)out_size;
    const float* x    = (const float*)d_in[0];
    const float* kern = (const float*)d_in[1];
    const float* bias = (const float*)d_in[2];
    float* out = (float*)d_out;

    wt_transform<<<(COUT * KTOT + 255) / 256, 256>>>(kern);

    cudaFuncSetAttribute(conv_mma, cudaFuncAttributeMaxDynamicSharedMemorySize, SMEM_BYTES);
    dim3 grid((WW / 128) * (COUT / 128), HH, 8);   // (4, 256, 8) = 8192 CTAs
    conv_mma<<<grid, 256, SMEM_BYTES>>>(x, bias, out);
}

// round 11
// speedup vs baseline: 3.8801x; 1.0294x over previous
#include <cuda_runtime.h>
#include <cstdint>

// SplitContextCenterConv2D as implicit GEMM on warp-level tf32 mma.sync.
// GEMM: M = 8*256*256 pixels, N = 256, K = 9*128 = 1152 (36 chunks of 32).
// CTA tile 128x128, 2 CTAs/SM, full unroll, 1 barrier/chunk.
// This round: hoist ALL loop-invariant address math / predicates into
// registers so each chunk's prefetch is ~8 LDGSTS with reg+imm addressing.

#define HH 256
#define WW 256
#define CIN 128
#define COUT 256
#define KTOT 1152
#define NCHUNK 36

#define STRIDE 40                    // floats per smem row (conflict-free)
#define A_FLOATS (128 * STRIDE)      // 5120
#define B_FLOATS (128 * STRIDE)
#define STAGE_FLOATS (A_FLOATS + B_FLOATS)
#define SMEM_BYTES (2 * STAGE_FLOATS * 4)   // 81920

__device__ float g_wt[COUT * KTOT];  // tf32(rna) bit patterns, layout [n][k]

static __device__ __forceinline__ uint32_t f2tf32(float f) {
    uint32_t r;
    asm("cvt.rna.tf32.f32 %0, %1;" : "=r"(r) : "f"(f));
    return r;
}

__global__ void wt_transform(const float* __restrict__ kern) {
    int o = blockIdx.x * 256 + threadIdx.x;
    if (o >= COUT * KTOT) return;
    int n = o / KTOT;
    int k = o - n * KTOT;
    int t = k >> 7;
    int ci = k & 127;
    int io = (t == 4) ? 1 : 0;
    float v = kern[(size_t)((t * 2 + io) * CIN + ci) * COUT + n];
    g_wt[o] = __uint_as_float(f2tf32(v));
}

static __device__ __forceinline__ void cp16(uint32_t dst, const void* src, uint32_t sz) {
    asm volatile("cp.async.cg.shared.global [%0], [%1], 16, %2;"
                 :: "r"(dst), "l"(src), "r"(sz) : "memory");
}

__global__ __launch_bounds__(256, 2)
void conv_mma(const float* __restrict__ x, const float* __restrict__ bias,
              float* __restrict__ out) {
    extern __shared__ float smem[];
    const uint32_t smem_b = (uint32_t)__cvta_generic_to_shared(smem);

    const int tid  = threadIdx.x;
    const int wid  = tid >> 5;
    const int lane = tid & 31;
    const int g    = lane >> 2;   // 0..7
    const int tig  = lane & 3;    // 0..3

    const int m0 = (wid & 1) * 64;   // warp M offset
    const int n0 = (wid >> 1) * 32;  // warp N offset

    const int b  = blockIdx.z;
    const int h  = blockIdx.y;
    const int w0 = (blockIdx.x >> 1) * 128;
    const int nb = (blockIdx.x & 1) * 128;      // N half
    const size_t img = (size_t)b * HH * WW * COUT;

    // ---------------- hoisted invariants ----------------
    const int mbase = tid >> 3;          // 0..31 (A/B tile row, per i add 32)
    const int j4    = (tid & 7) * 4;     // float offset of 16B segment in k

    // central gmem pixel offsets (elements), kx==1
    int offC[4];
#pragma unroll
    for (int i = 0; i < 4; i++) offC[i] = (w0 + mbase + 32 * i) * COUT + j4;
    // boundary-clamped specials: only (i==0,kx==0) and (i==3,kx==2) can clip
    const int gwL0 = w0 + mbase - 1;
    const uint32_t szL0 = (gwL0 >= 0) ? 16u : 0u;
    const int offL0 = (gwL0 >= 0 ? gwL0 : 0) * COUT + j4;
    const int gwR3 = w0 + mbase + 97;
    const uint32_t szR3 = (gwR3 < WW) ? 16u : 0u;
    const int offR3 = (gwR3 < WW ? gwR3 : WW - 1) * COUT + j4;

    // clamped row base pointers + validity (ky = 0,1,2)
    const float* rowPtr[3];
    uint32_t rowSz[3];
#pragma unroll
    for (int r = 0; r < 3; r++) {
        int gh = h - 1 + r;
        bool ok = (unsigned)gh < (unsigned)HH;
        rowPtr[r] = x + img + (size_t)(ok ? gh : 0) * WW * COUT;
        rowSz[r] = ok ? 16u : 0u;
    }

    // smem dst byte offsets (same for A and B regions)
    uint32_t sdA[4];
#pragma unroll
    for (int i = 0; i < 4; i++)
        sdA[i] = (uint32_t)(((mbase + 32 * i) * STRIDE + j4) * 4);

    // B gmem element offsets (add c*32 imm per chunk)
    int bOff[4];
#pragma unroll
    for (int i = 0; i < 4; i++) bOff[i] = (nb + mbase + 32 * i) * KTOT + j4;

    // fragment smem float offsets (add k0 + stage imm per use)
    int fA[4], fB[4];
#pragma unroll
    for (int mi = 0; mi < 4; mi++) fA[mi] = (m0 + mi * 16 + g) * STRIDE + 2 * tig;
#pragma unroll
    for (int ni = 0; ni < 4; ni++) fB[ni] = (n0 + ni * 8 + g) * STRIDE + 2 * tig;

    float acc[4][4][4];
#pragma unroll
    for (int mi = 0; mi < 4; mi++)
#pragma unroll
        for (int ni = 0; ni < 4; ni++)
#pragma unroll
            for (int r = 0; r < 4; r++) acc[mi][ni][r] = 0.f;

    auto prefetch = [&](int c) {   // c is compile-time after full unroll
        const uint32_t stOff = (uint32_t)((c & 1) * (STAGE_FLOATS * 4));
        const int t   = c >> 2;
        const int ci0 = (c & 3) << 5;
        const bool cen = (t == 4);
        const int ky = t / 3, kx = t % 3;

        const float* base = cen ? (rowPtr[1] + CIN + ci0) : (rowPtr[ky] + ci0);
        const uint32_t rsz = cen ? 16u : rowSz[ky];

#pragma unroll
        for (int i = 0; i < 4; i++) {
            int off;
            uint32_t sz;
            if (cen || kx == 1) { off = offC[i]; sz = rsz; }
            else if (kx == 0) {
                off = (i == 0) ? offL0 : (offC[i] - COUT);
                sz  = (i == 0) ? (szL0 & rsz) : rsz;
            } else {
                off = (i == 3) ? offR3 : (offC[i] + COUT);
                sz  = (i == 3) ? (szR3 & rsz) : rsz;
            }
            cp16(smem_b + stOff + sdA[i], base + off, sz);
        }
        const float* wbase = g_wt + c * 32;
#pragma unroll
        for (int i = 0; i < 4; i++)
            cp16(smem_b + stOff + (uint32_t)(A_FLOATS * 4) + sdA[i],
                 wbase + bOff[i], 16);
        asm volatile("cp.async.commit_group;" ::: "memory");
    };

    prefetch(0);

#pragma unroll
    for (int c = 0; c < NCHUNK; c++) {
        asm volatile("cp.async.wait_group 0;" ::: "memory");
        __syncthreads();
        if (c + 1 < NCHUNK) prefetch(c + 1);

        const float* sA = smem + (c & 1) * STAGE_FLOATS;
        const float* sB = sA + A_FLOATS;

        // k-slot pairing: smem pos 2t -> MMA slot t, 2t+1 -> slot t+4 on
        // both operands (contraction order within k is free).
#pragma unroll
        for (int kk = 0; kk < 4; kk++) {
            const int k0 = kk * 8;
            float2 aF[4][2];
#pragma unroll
            for (int mi = 0; mi < 4; mi++) {
                const float* ap = sA + fA[mi] + k0;
                aF[mi][0] = *(const float2*)ap;
                aF[mi][1] = *(const float2*)(ap + 8 * STRIDE);
            }
            float2 bF[4];
#pragma unroll
            for (int ni = 0; ni < 4; ni++)
                bF[ni] = *(const float2*)(sB + fB[ni] + k0);
#pragma unroll
            for (int mi = 0; mi < 4; mi++)
#pragma unroll
                for (int ni = 0; ni < 4; ni++)
                    asm volatile(
                        "mma.sync.aligned.m16n8k8.row.col.f32.tf32.tf32.f32 "
                        "{%0,%1,%2,%3}, {%4,%5,%6,%7}, {%8,%9}, {%0,%1,%2,%3};"
                        : "+f"(acc[mi][ni][0]), "+f"(acc[mi][ni][1]),
                          "+f"(acc[mi][ni][2]), "+f"(acc[mi][ni][3])
                        : "f"(aF[mi][0].x), "f"(aF[mi][1].x),
                          "f"(aF[mi][0].y), "f"(aF[mi][1].y),
                          "f"(bF[ni].x), "f"(bF[ni].y));
        }
    }

    // ---------------- epilogue ----------------
    float bv[4][2];
#pragma unroll
    for (int ni = 0; ni < 4; ni++) {
        int n = nb + n0 + ni * 8 + tig * 2;
        bv[ni][0] = bias[n];
        bv[ni][1] = bias[n + 1];
    }
#pragma unroll
    for (int mi = 0; mi < 4; mi++) {
        int r0 = m0 + mi * 16 + g;
        float* p0 = out + img + ((size_t)h * WW + (w0 + r0)) * COUT;
        float* p1 = out + img + ((size_t)h * WW + (w0 + r0 + 8)) * COUT;
#pragma unroll
        for (int ni = 0; ni < 4; ni++) {
            int n = nb + n0 + ni * 8 + tig * 2;
            float2 v0 = make_float2(acc[mi][ni][0] + bv[ni][0],
                                    acc[mi][ni][1] + bv[ni][1]);
            float2 v1 = make_float2(acc[mi][ni][2] + bv[ni][0],
                                    acc[mi][ni][3] + bv[ni][1]);
            *(float2*)(p0 + n) = v0;
            *(float2*)(p1 + n) = v1;
        }
    }
}

extern "C" void kernel_launch(void* const* d_in, const int* in_sizes, int n_in,
                              void* d_out, int out_size) {
    (void)in_sizes; (void)n_in; (void)out_size;
    const float* x    = (const float*)d_in[0];
    const float* kern = (const float*)d_in[1];
    const float* bias = (const float*)d_in[2];
    float* out = (float*)d_out;

    wt_transform<<<(COUT * KTOT + 255) / 256, 256>>>(kern);

    cudaFuncSetAttribute(conv_mma, cudaFuncAttributeMaxDynamicSharedMemorySize, SMEM_BYTES);
    dim3 grid((WW / 128) * (COUT / 128), HH, 8);   // (4, 256, 8) = 8192 CTAs
    conv_mma<<<grid, 256, SMEM_BYTES>>>(x, bias, out);
}

// round 13
// speedup vs baseline: 5.9263x; 1.5274x over previous
#include <cuda_runtime.h>
#include <cuda_fp16.h>
#include <cstdint>

// SplitContextCenterConv2D as implicit GEMM on warp-level fp16 mma.sync
// (m16n8k16.f32.f16.f16.f32): fp16 carries the same 10 mantissa bits as
// tf32, so precision matches the tf32 path while MMA count halves.
// GEMM: M = 8*256*256 pixels, N = 256, K = 9*128 = 1152 (36 chunks of 32).
// CTA tile 128x128, 2 CTAs/SM, full unroll, 1 barrier/chunk.
// A: LDG.128 -> cvt.f16x2 -> STS.64 (software pipelined); B: pre-converted
// fp16 weights via cp.async. SMEM row stride 48 fp16 (96B) = conflict-free.

#define HH 256
#define WW 256
#define CIN 128
#define COUT 256
#define KTOT 1152
#define NCHUNK 36

#define STRIDE_H 48                    // fp16 per smem row (96B)
#define A_BYTES (128 * STRIDE_H * 2)   // 12288
#define STAGE_BYTES (2 * A_BYTES)      // 24576 (A + B)
#define SMEM_BYTES (2 * STAGE_BYTES)   // 49152

__device__ __half g_wt16[COUT * KTOT];   // fp16 weights, layout [n][k]

__global__ void wt_transform(const float* __restrict__ kern) {
    int o = blockIdx.x * 256 + threadIdx.x;
    if (o >= COUT * KTOT) return;
    int n = o / KTOT;
    int k = o - n * KTOT;
    int t = k >> 7;
    int ci = k & 127;
    int io = (t == 4) ? 1 : 0;
    float v = kern[(size_t)((t * 2 + io) * CIN + ci) * COUT + n];
    g_wt16[o] = __float2half_rn(v);
}

static __device__ __forceinline__ void cp16(uint32_t dst, const void* src) {
    asm volatile("cp.async.cg.shared.global [%0], [%1], 16;"
                 :: "r"(dst), "l"(src) : "memory");
}
static __device__ __forceinline__ uint32_t pack_h2(float lo, float hi) {
    uint32_t r;
    asm("cvt.rn.f16x2.f32 %0, %1, %2;" : "=r"(r) : "f"(hi), "f"(lo));
    return r;
}

__global__ __launch_bounds__(256, 2)
void conv_mma(const float* __restrict__ x, const float* __restrict__ bias,
              float* __restrict__ out) {
    extern __shared__ char smem[];
    const uint32_t smem_b = (uint32_t)__cvta_generic_to_shared(smem);

    const int tid  = threadIdx.x;
    const int wid  = tid >> 5;
    const int lane = tid & 31;
    const int g    = lane >> 2;   // 0..7
    const int tig  = lane & 3;    // 0..3

    const int m0 = (wid & 1) * 64;   // warp M offset
    const int n0 = (wid >> 1) * 32;  // warp N offset

    const int b  = blockIdx.z;
    const int h  = blockIdx.y;
    const int w0 = (blockIdx.x >> 1) * 128;
    const int nb = (blockIdx.x & 1) * 128;      // N half
    const size_t img = (size_t)b * HH * WW * COUT;

    // ---------------- hoisted invariants ----------------
    const int mbase = tid >> 3;          // 0..31 (+32 per i)
    const int jk    = tid & 7;           // k-segment (4 floats)

    int offC[4];                          // central (kx==1) gmem offsets
#pragma unroll
    for (int i = 0; i < 4; i++) offC[i] = (w0 + mbase + 32 * i) * COUT + jk * 4;
    const int gwL0 = w0 + mbase - 1;               // (i==0, kx==0)
    const bool okL0 = (gwL0 >= 0);
    const int offL0 = (okL0 ? gwL0 : 0) * COUT + jk * 4;
    const int gwR3 = w0 + mbase + 97;              // (i==3, kx==2)
    const bool okR3 = (gwR3 < WW);
    const int offR3 = (okR3 ? gwR3 : WW - 1) * COUT + jk * 4;

    const float* rowPtr[3];
    bool rowOk[3];
#pragma unroll
    for (int r = 0; r < 3; r++) {
        int gh = h - 1 + r;
        rowOk[r] = (unsigned)gh < (unsigned)HH;
        rowPtr[r] = x + img + (size_t)(rowOk[r] ? gh : 0) * WW * COUT;
    }

    // A smem dst byte offsets: row*96 + jk*8  (4 fp16 per seg)
    uint32_t sdA[4];
#pragma unroll
    for (int i = 0; i < 4; i++)
        sdA[i] = (uint32_t)((mbase + 32 * i) * (STRIDE_H * 2) + jk * 8);

    // B: 2 cp.async segs/thread: row = e>>2, seg = e&3 (16B = 8 fp16)
    const int bRow0 = tid >> 2;          // rows 0..63  (e = tid)
    const int bSeg  = tid & 3;
    uint32_t sdB[2];
    int bOff[2];
#pragma unroll
    for (int i = 0; i < 2; i++) {
        int row = bRow0 + 64 * i;
        sdB[i] = (uint32_t)(A_BYTES + row * (STRIDE_H * 2) + bSeg * 16);
        bOff[i] = (nb + row) * KTOT + bSeg * 8;
    }

    // fragment smem byte offsets
    uint32_t fA[4], fB[4];
#pragma unroll
    for (int mi = 0; mi < 4; mi++)
        fA[mi] = (uint32_t)((m0 + mi * 16 + g) * (STRIDE_H * 2) + tig * 8);
#pragma unroll
    for (int ni = 0; ni < 4; ni++)
        fB[ni] = (uint32_t)(A_BYTES + (n0 + ni * 8 + g) * (STRIDE_H * 2) + tig * 8);

    float acc[4][4][4];
#pragma unroll
    for (int mi = 0; mi < 4; mi++)
#pragma unroll
        for (int ni = 0; ni < 4; ni++)
#pragma unroll
            for (int r = 0; r < 4; r++) acc[mi][ni][r] = 0.f;

    float4 va[4];   // in-flight A data for next chunk

    auto ldgA = [&](int c) {     // c compile-time after unroll
        const int t   = c >> 2;
        const int ci0 = (c & 3) << 5;
        const bool cen = (t == 4);
        const int ky = t / 3, kx = t % 3;
        const float* base = cen ? (rowPtr[1] + CIN + ci0) : (rowPtr[ky] + ci0);
        const bool rok = cen ? true : rowOk[ky];
#pragma unroll
        for (int i = 0; i < 4; i++) {
            int off; bool ok;
            if (cen || kx == 1) { off = offC[i]; ok = rok; }
            else if (kx == 0) {
                off = (i == 0) ? offL0 : (offC[i] - COUT);
                ok  = (i == 0) ? (okL0 && rok) : rok;
            } else {
                off = (i == 3) ? offR3 : (offC[i] + COUT);
                ok  = (i == 3) ? (okR3 && rok) : rok;
            }
            va[i] = make_float4(0.f, 0.f, 0.f, 0.f);
            if (ok) va[i] = *(const float4*)(base + off);
        }
    };
    auto cpB = [&](int c) {
        const uint32_t st = smem_b + (uint32_t)((c & 1) * STAGE_BYTES);
        const __half* wbase = g_wt16 + c * 32;
#pragma unroll
        for (int i = 0; i < 2; i++)
            cp16(st + sdB[i], wbase + bOff[i]);
        asm volatile("cp.async.commit_group;" ::: "memory");
    };
    auto stsA = [&](int c) {
        const uint32_t st = smem_b + (uint32_t)((c & 1) * STAGE_BYTES);
#pragma unroll
        for (int i = 0; i < 4; i++) {
            uint32_t h0 = pack_h2(va[i].x, va[i].y);
            uint32_t h1 = pack_h2(va[i].z, va[i].w);
            asm volatile("st.shared.v2.b32 [%0], {%1, %2};"
                         :: "r"(st + sdA[i]), "r"(h0), "r"(h1) : "memory");
        }
    };

    // prologue: fill stage 0
    ldgA(0); cpB(0); stsA(0);
    asm volatile("cp.async.wait_group 0;" ::: "memory");
    __syncthreads();

#pragma unroll
    for (int c = 0; c < NCHUNK; c++) {
        if (c + 1 < NCHUNK) { ldgA(c + 1); cpB(c + 1); }

        const uint32_t st = smem_b + (uint32_t)((c & 1) * STAGE_BYTES);

        // k-slot mapping: smem pos 4t,4t+1 -> slots 2t,2t+1; 4t+2,4t+3 ->
        // slots 2t+8,2t+9 — identical on A and B, so one LDS.64 yields
        // (a0,a2) / (a1,a3) / (b0,b1).
#pragma unroll
        for (int ks = 0; ks < 2; ks++) {
            uint32_t aF[4][4];   // [mi][a0,a1,a2,a3]
#pragma unroll
            for (int mi = 0; mi < 4; mi++) {
                asm volatile("ld.shared.v2.b32 {%0, %1}, [%2];"
                             : "=r"(aF[mi][0]), "=r"(aF[mi][2])
                             : "r"(st + fA[mi] + ks * 32));
                asm volatile("ld.shared.v2.b32 {%0, %1}, [%2];"
                             : "=r"(aF[mi][1]), "=r"(aF[mi][3])
                             : "r"(st + fA[mi] + 8 * (STRIDE_H * 2) + ks * 32));
            }
            uint32_t bF[4][2];
#pragma unroll
            for (int ni = 0; ni < 4; ni++)
                asm volatile("ld.shared.v2.b32 {%0, %1}, [%2];"
                             : "=r"(bF[ni][0]), "=r"(bF[ni][1])
                             : "r"(st + fB[ni] + ks * 32));
#pragma unroll
            for (int mi = 0; mi < 4; mi++)
#pragma unroll
                for (int ni = 0; ni < 4; ni++)
                    asm volatile(
                        "mma.sync.aligned.m16n8k16.row.col.f32.f16.f16.f32 "
                        "{%0,%1,%2,%3}, {%4,%5,%6,%7}, {%8,%9}, {%0,%1,%2,%3};"
                        : "+f"(acc[mi][ni][0]), "+f"(acc[mi][ni][1]),
                          "+f"(acc[mi][ni][2]), "+f"(acc[mi][ni][3])
                        : "r"(aF[mi][0]), "r"(aF[mi][1]),
                          "r"(aF[mi][2]), "r"(aF[mi][3]),
                          "r"(bF[ni][0]), "r"(bF[ni][1]));
        }

        if (c + 1 < NCHUNK) stsA(c + 1);
        asm volatile("cp.async.wait_group 0;" ::: "memory");
        __syncthreads();
    }

    // ---------------- epilogue ----------------
    float bv[4][2];
#pragma unroll
    for (int ni = 0; ni < 4; ni++) {
        int n = nb + n0 + ni * 8 + tig * 2;
        bv[ni][0] = bias[n];
        bv[ni][1] = bias[n + 1];
    }
#pragma unroll
    for (int mi = 0; mi < 4; mi++) {
        int r0 = m0 + mi * 16 + g;
        float* p0 = out + img + ((size_t)h * WW + (w0 + r0)) * COUT;
        float* p1 = out + img + ((size_t)h * WW + (w0 + r0 + 8)) * COUT;
#pragma unroll
        for (int ni = 0; ni < 4; ni++) {
            int n = nb + n0 + ni * 8 + tig * 2;
            float2 v0 = make_float2(acc[mi][ni][0] + bv[ni][0],
                                    acc[mi][ni][1] + bv[ni][1]);
            float2 v1 = make_float2(acc[mi][ni][2] + bv[ni][0],
                                    acc[mi][ni][3] + bv[ni][1]);
            *(float2*)(p0 + n) = v0;
            *(float2*)(p1 + n) = v1;
        }
    }
}

extern "C" void kernel_launch(void* const* d_in, const int* in_sizes, int n_in,
                              void* d_out, int out_size) {
    (void)in_sizes; (void)n_in; (void)out_size;
    const float* x    = (const float*)d_in[0];
    const float* kern = (const float*)d_in[1];
    const float* bias = (const float*)d_in[2];
    float* out = (float*)d_out;

    wt_transform<<<(COUT * KTOT + 255) / 256, 256>>>(kern);

    cudaFuncSetAttribute(conv_mma, cudaFuncAttributeMaxDynamicSharedMemorySize, SMEM_BYTES);
    dim3 grid((WW / 128) * (COUT / 128), HH, 8);   // (4, 256, 8) = 8192 CTAs
    conv_mma<<<grid, 256, SMEM_BYTES>>>(x, bias, out);
}